// round 4
// baseline (speedup 1.0000x reference)
#include <cuda_runtime.h>
#include <cstdint>

// out[b, 0:128]   = x[b, :]                       for b < B
// out[b, 128:256] = sum_{e: dst[e]==b} x[src[e]]
//
// Pipeline:
//   memset:  zero per-row counters + overflow counter (graph memset nodes).
//   K1 bin:  ELL binning by destination, int4-vectorized edge loads.
//   K2 main: one warp per row: register-accumulate gathered neighbors,
//            fused copy of x[b]; rows overflowing SLOTS scan the overflow
//            list in-warp (expected empty). Plain STG.128 stores, no atomics.

#define NFEAT   128
#define ROW_OUT 256
#define MAX_E   640000
#define B_MAX   65536
#define SLOTS   32

__device__ int  g_cnt[B_MAX];
__device__ int  g_ell[B_MAX * SLOTS];
__device__ int2 g_ovf[MAX_E];
__device__ int  g_ovf_count;

__global__ void bin_kernel(const int* __restrict__ ei, int E, int B) {
    int i = blockIdx.x * blockDim.x + threadIdx.x;   // over E/4 quads
    int nq = E >> 2;
    if (i >= nq) return;
    int4 s4 = __ldg(reinterpret_cast<const int4*>(ei) + i);
    int4 d4 = __ldg(reinterpret_cast<const int4*>(ei + E) + i);
    int ss[4] = {s4.x, s4.y, s4.z, s4.w};
    int dd[4] = {d4.x, d4.y, d4.z, d4.w};
    #pragma unroll
    for (int j = 0; j < 4; j++) {
        int d = dd[j];
        if ((unsigned)d < (unsigned)B) {
            int k = atomicAdd(&g_cnt[d], 1);
            if (k < SLOTS) {
                g_ell[d * SLOTS + k] = ss[j];
            } else {
                int p = atomicAdd(&g_ovf_count, 1);
                g_ovf[p] = make_int2(ss[j], d);
            }
        }
    }
}

__global__ void main_kernel(const float* __restrict__ x,
                            float* __restrict__ out,
                            int B) {
    int warp = (blockIdx.x * blockDim.x + threadIdx.x) >> 5;
    int lane = threadIdx.x & 31;
    if (warp >= B) return;
    int b = warp;

    int c_raw = g_cnt[b];
    int c = c_raw < SLOTS ? c_raw : SLOTS;

    // Coalesced preload of this row's source list (one slot per lane).
    int src_l = (lane < c) ? g_ell[b * SLOTS + lane] : 0;

    float4 acc = make_float4(0.f, 0.f, 0.f, 0.f);
    for (int k = 0; k < c; k++) {
        int se = __shfl_sync(0xFFFFFFFFu, src_l, k);
        float4 v = __ldg(reinterpret_cast<const float4*>(
                             x + (size_t)se * NFEAT) + lane);
        acc.x += v.x; acc.y += v.y; acc.z += v.z; acc.w += v.w;
    }

    // Rare path: this row's degree exceeded SLOTS -> its extras are in the
    // overflow list. Same warp accumulates them before the store (no race).
    if (c_raw > SLOTS) {
        int n = g_ovf_count;
        for (int e = 0; e < n; e++) {
            int2 ed = g_ovf[e];            // uniform broadcast read
            if (ed.y == b) {
                float4 v = __ldg(reinterpret_cast<const float4*>(
                                     x + (size_t)ed.x * NFEAT) + lane);
                acc.x += v.x; acc.y += v.y; acc.z += v.z; acc.w += v.w;
            }
        }
    }

    // Fused: first half = x[b], second half = neighbor sum.
    float4 mine = __ldg(reinterpret_cast<const float4*>(
                            x + (size_t)b * NFEAT) + lane);
    float4* orow = reinterpret_cast<float4*>(out + (size_t)b * ROW_OUT);
    orow[lane]                = mine;
    orow[(NFEAT / 4) + lane]  = acc;
}

extern "C" void kernel_launch(void* const* d_in, const int* in_sizes, int n_in,
                              void* d_out, int out_size) {
    const float* x        = (const float*)d_in[0];
    const int*   edge_idx = (const int*)d_in[1];
    float*       out      = (float*)d_out;

    int B = out_size / ROW_OUT;          // 50000
    int E = in_sizes[1] / 2;             // 640000

    // Zero counters via graph-capturable memset nodes (no kernel launch).
    void* p_cnt = nullptr;
    void* p_ovfc = nullptr;
    cudaGetSymbolAddress(&p_cnt, g_cnt);
    cudaGetSymbolAddress(&p_ovfc, g_ovf_count);
    cudaMemsetAsync(p_cnt, 0, (size_t)B * sizeof(int));
    cudaMemsetAsync(p_ovfc, 0, sizeof(int));

    {   // K1: ELL binning (4 edges per thread)
        int nq = E >> 2;
        int threads = 256;
        int blocks = (nq + threads - 1) / threads;
        bin_kernel<<<blocks, threads>>>(edge_idx, E, B);
    }
    {   // K2: main fused gather-accumulate-store, one warp per row
        int threads = 256;                          // 8 warps/block
        int blocks = (B + 7) / 8;
        main_kernel<<<blocks, threads>>>(x, out, B);
    }
}